// round 1
// baseline (speedup 1.0000x reference)
#include <cuda_runtime.h>
#include <cuda_bf16.h>
#include <cstdint>

typedef unsigned long long ull;

// ---------------------------------------------------------------------------
// Packed fp32x2 helpers (Blackwell sm_100+: fma.rn.f32x2 — PTX-only path,
// doubles fp32 FMA throughput vs scalar FFMA on sm_103a)
// ---------------------------------------------------------------------------
__device__ __forceinline__ void fma2(ull& d, ull a, ull b) {
    asm("fma.rn.f32x2 %0, %1, %2, %0;" : "+l"(d) : "l"(a), "l"(b));
}
__device__ __forceinline__ void mul2(ull& d, ull a) {
    asm("mul.rn.f32x2 %0, %0, %1;" : "+l"(d) : "l"(a));
}
__device__ __forceinline__ void add2(ull& d, ull a) {
    asm("add.rn.f32x2 %0, %0, %1;" : "+l"(d) : "l"(a));
}
__device__ __forceinline__ ull dup2(float x) {
    ull r; asm("mov.b64 %0, {%1, %1};" : "=l"(r) : "f"(x)); return r;
}
__device__ __forceinline__ void unpack2(ull v, float& lo, float& hi) {
    asm("mov.b64 {%0, %1}, %2;" : "=f"(lo), "=f"(hi) : "l"(v));
}

// ---------------------------------------------------------------------------
// Problem constants
// ---------------------------------------------------------------------------
#define BATCH   4
#define S_LEN   2048
#define EMB     1024
#define NHEAD   16
#define DHEAD   64
#define MROWS   (BATCH * S_LEN)   // 8192

// Scratch (device-global: no allocations allowed)
__device__ float g_Qp[MROWS * EMB];
__device__ float g_Kp[MROWS * EMB];
__device__ float g_Vp[MROWS * EMB];
__device__ float g_Ctx[MROWS * EMB];

// ---------------------------------------------------------------------------
// SGEMM-NT:  C[m][n] = sum_k A[m][k] * B[n][k]  (+ bias[n])
// BM=BN=128, BK=16, 256 threads, 8x8 per-thread tile, f32x2 packed FMAs.
// ---------------------------------------------------------------------------
__global__ __launch_bounds__(256, 2) void sgemm_nt_kernel(
    const float* __restrict__ A, const float* __restrict__ B,
    const float* __restrict__ bias, float* __restrict__ C,
    int M, int N, int K)
{
    __shared__ float As[16][128];
    __shared__ float Bs[16][128];

    const int t  = threadIdx.x;
    const int bm = blockIdx.y * 128;
    const int bn = blockIdx.x * 128;
    const int tx = t & 15;        // n-dir
    const int ty = t >> 4;        // m-dir

    ull acc[8][4];
    #pragma unroll
    for (int i = 0; i < 8; i++)
        #pragma unroll
        for (int j = 0; j < 4; j++) acc[i][j] = 0ull;

    const int lr = t >> 2;           // load row 0..63 (and +64)
    const int lc = (t & 3) * 4;      // load col 0..12

    const float* Aptr = A + (size_t)(bm + lr) * K + lc;
    const float* Bptr = B + (size_t)(bn + lr) * K + lc;

    for (int k0 = 0; k0 < K; k0 += 16) {
        float4 a0 = *(const float4*)(Aptr + k0);
        float4 a1 = *(const float4*)(Aptr + (size_t)64 * K + k0);
        float4 b0 = *(const float4*)(Bptr + k0);
        float4 b1 = *(const float4*)(Bptr + (size_t)64 * K + k0);

        __syncthreads();
        As[lc + 0][lr] = a0.x;  As[lc + 1][lr] = a0.y;
        As[lc + 2][lr] = a0.z;  As[lc + 3][lr] = a0.w;
        As[lc + 0][lr + 64] = a1.x;  As[lc + 1][lr + 64] = a1.y;
        As[lc + 2][lr + 64] = a1.z;  As[lc + 3][lr + 64] = a1.w;
        Bs[lc + 0][lr] = b0.x;  Bs[lc + 1][lr] = b0.y;
        Bs[lc + 2][lr] = b0.z;  Bs[lc + 3][lr] = b0.w;
        Bs[lc + 0][lr + 64] = b1.x;  Bs[lc + 1][lr + 64] = b1.y;
        Bs[lc + 2][lr + 64] = b1.z;  Bs[lc + 3][lr + 64] = b1.w;
        __syncthreads();

        #pragma unroll
        for (int kk = 0; kk < 16; kk++) {
            float4 av0 = *(const float4*)&As[kk][ty * 8];
            float4 av1 = *(const float4*)&As[kk][ty * 8 + 4];
            ulonglong2 bv0 = *(const ulonglong2*)&Bs[kk][tx * 8];
            ulonglong2 bv1 = *(const ulonglong2*)&Bs[kk][tx * 8 + 4];
            ull b4[4] = { bv0.x, bv0.y, bv1.x, bv1.y };
            float a8[8] = { av0.x, av0.y, av0.z, av0.w,
                            av1.x, av1.y, av1.z, av1.w };
            #pragma unroll
            for (int i = 0; i < 8; i++) {
                ull ad = dup2(a8[i]);
                #pragma unroll
                for (int j = 0; j < 4; j++) fma2(acc[i][j], ad, b4[j]);
            }
        }
    }

    // epilogue
    #pragma unroll
    for (int i = 0; i < 8; i++) {
        float* Crow = C + (size_t)(bm + ty * 8 + i) * N + bn + tx * 8;
        if (bias) {
            #pragma unroll
            for (int j = 0; j < 4; j++) {
                ull bb = *(const ull*)&bias[bn + tx * 8 + j * 2];
                add2(acc[i][j], bb);
                *(ull*)&Crow[j * 2] = acc[i][j];
            }
        } else {
            #pragma unroll
            for (int j = 0; j < 4; j++) *(ull*)&Crow[j * 2] = acc[i][j];
        }
    }
}

// ---------------------------------------------------------------------------
// Flash attention, fp32.  Grid: (S/128, B*H).  128 threads, 1 query/thread.
// Br=128 queries/CTA, Bc=64 keys/tile.  K tile stored d-major (transposed)
// so scores are broadcast-LDS.128 + f32x2 FMA; V tile natural; online softmax
// entirely thread-local (each thread owns a full query row).
// ---------------------------------------------------------------------------
#define BR 128
#define BC 64

__global__ __launch_bounds__(128) void attn_kernel(
    const float* __restrict__ Qp, const float* __restrict__ Kp,
    const float* __restrict__ Vp, const int* __restrict__ mask,
    float* __restrict__ Ctx)
{
    extern __shared__ float sm[];
    float* QsT = sm;                         // [64][128]  d-major Q
    float* KsT = sm + 64 * 128;              // [64][64]   d-major K
    float* Vs  = KsT + 64 * 64;              // [64][64]   key-major V
    int*   msk = (int*)(Vs + 64 * 64);       // [64]

    const int t  = threadIdx.x;
    const int qt = blockIdx.x;               // query tile 0..15
    const int bh = blockIdx.y;               // 0..63
    const int b  = bh >> 4;
    const int h  = bh & 15;
    const int q0 = qt * BR;

    // ---- load Q tile transposed: QsT[d][q] (conflict-free STS) ----
    {
        const float* Qbase = Qp + ((size_t)(b * S_LEN + q0)) * EMB + h * DHEAD;
        #pragma unroll
        for (int i = 0; i < 16; i++) {
            int f  = t + 128 * i;        // float4 index, 2048 total
            int d4 = f >> 7;             // 0..15
            int q  = f & 127;
            float4 v = *(const float4*)(Qbase + (size_t)q * EMB + d4 * 4);
            QsT[(d4 * 4 + 0) * 128 + q] = v.x;
            QsT[(d4 * 4 + 1) * 128 + q] = v.y;
            QsT[(d4 * 4 + 2) * 128 + q] = v.z;
            QsT[(d4 * 4 + 3) * 128 + q] = v.w;
        }
    }

    ull o2[32];
    #pragma unroll
    for (int i = 0; i < 32; i++) o2[i] = 0ull;
    float m_run = -1e30f, l_run = 0.0f;

    for (int kt = 0; kt < S_LEN / BC; kt++) {
        const int k0 = kt * BC;
        __syncthreads();   // protect previous iteration's K/V reads (and Q store 1st iter)

        // ---- load K (d-major) and V (key-major) tiles + mask ----
        const float* Kbase = Kp + ((size_t)(b * S_LEN + k0)) * EMB + h * DHEAD;
        const float* Vbase = Vp + ((size_t)(b * S_LEN + k0)) * EMB + h * DHEAD;
        #pragma unroll
        for (int i = 0; i < 8; i++) {
            int f = t + 128 * i;         // float4 index, 1024 total
            int d4  = f >> 6;            // 0..15
            int key = f & 63;
            float4 kv = *(const float4*)(Kbase + (size_t)key * EMB + d4 * 4);
            KsT[(d4 * 4 + 0) * 64 + key] = kv.x;
            KsT[(d4 * 4 + 1) * 64 + key] = kv.y;
            KsT[(d4 * 4 + 2) * 64 + key] = kv.z;
            KsT[(d4 * 4 + 3) * 64 + key] = kv.w;
            int vk  = f >> 4;            // 0..63
            int vd4 = f & 15;
            float4 vv = *(const float4*)(Vbase + (size_t)vk * EMB + vd4 * 4);
            *(float4*)&Vs[vk * 64 + vd4 * 4] = vv;
        }
        if (t < 64) msk[t] = mask[b * S_LEN + k0 + t];
        __syncthreads();

        // ---- scores: s[j] = sum_d Q[q][d] * K[j][d] ----
        ull s2[32];
        #pragma unroll
        for (int j2 = 0; j2 < 32; j2++) s2[j2] = 0ull;
        #pragma unroll 8
        for (int d = 0; d < 64; d++) {
            ull qd = dup2(QsT[d * 128 + t]);
            const ulonglong2* kr = (const ulonglong2*)&KsT[d * 64];
            #pragma unroll
            for (int j4 = 0; j4 < 16; j4++) {
                ulonglong2 kk = kr[j4];
                fma2(s2[j4 * 2 + 0], qd, kk.x);
                fma2(s2[j4 * 2 + 1], qd, kk.y);
            }
        }

        // ---- scale + mask + online softmax (thread-local) ----
        float sc[64];
        #pragma unroll
        for (int j2 = 0; j2 < 32; j2++)
            unpack2(s2[j2], sc[2 * j2], sc[2 * j2 + 1]);

        float mx = m_run;
        #pragma unroll
        for (int j = 0; j < 64; j++) {
            sc[j] = msk[j] ? sc[j] * 0.125f : -1e10f;
            mx = fmaxf(mx, sc[j]);
        }
        float corr = __expf(m_run - mx);
        m_run = mx;
        float lsum = 0.0f;
        #pragma unroll
        for (int j = 0; j < 64; j++) {
            float p = __expf(sc[j] - mx);
            sc[j] = p;
            lsum += p;
        }
        l_run = l_run * corr + lsum;

        ull c2 = dup2(corr);
        #pragma unroll
        for (int d2 = 0; d2 < 32; d2++) mul2(o2[d2], c2);

        // ---- O += P * V ----
        #pragma unroll 8
        for (int j = 0; j < 64; j++) {
            ull p2 = dup2(sc[j]);
            const ulonglong2* vr = (const ulonglong2*)&Vs[j * 64];
            #pragma unroll
            for (int d4 = 0; d4 < 16; d4++) {
                ulonglong2 vv = vr[d4];
                fma2(o2[d4 * 2 + 0], p2, vv.x);
                fma2(o2[d4 * 2 + 1], p2, vv.y);
            }
        }
    }

    // ---- epilogue: O / l -> Ctx[b][q][h*64+d] ----
    float inv = 1.0f / l_run;
    ull iv = dup2(inv);
    float* Crow = Ctx + ((size_t)(b * S_LEN + q0 + t)) * EMB + h * DHEAD;
    #pragma unroll
    for (int d2 = 0; d2 < 32; d2++) {
        mul2(o2[d2], iv);
        *(ull*)&Crow[d2 * 2] = o2[d2];
    }
}

// ---------------------------------------------------------------------------
// Launch
// ---------------------------------------------------------------------------
extern "C" void kernel_launch(void* const* d_in, const int* in_sizes, int n_in,
                              void* d_out, int out_size)
{
    const float* q    = (const float*)d_in[0];
    const float* k    = (const float*)d_in[1];
    const float* v    = (const float*)d_in[2];
    const int*   mask = (const int*)  d_in[3];
    const float* Wq   = (const float*)d_in[4];
    const float* Wk   = (const float*)d_in[5];
    const float* Wv   = (const float*)d_in[6];
    const float* Wo   = (const float*)d_in[7];
    const float* bo   = (const float*)d_in[8];
    float* out = (float*)d_out;

    float *Qp, *Kp, *Vp, *Ctx;
    cudaGetSymbolAddress((void**)&Qp,  g_Qp);
    cudaGetSymbolAddress((void**)&Kp,  g_Kp);
    cudaGetSymbolAddress((void**)&Vp,  g_Vp);
    cudaGetSymbolAddress((void**)&Ctx, g_Ctx);

    const int smem_attn = (64 * 128 + 64 * 64 + 64 * 64) * 4 + 64 * 4;
    cudaFuncSetAttribute(attn_kernel,
                         cudaFuncAttributeMaxDynamicSharedMemorySize, smem_attn);

    dim3 gGemm(EMB / 128, MROWS / 128);   // (8, 64)
    dim3 bGemm(256);

    sgemm_nt_kernel<<<gGemm, bGemm>>>(q, Wq, nullptr, Qp, MROWS, EMB, EMB);
    sgemm_nt_kernel<<<gGemm, bGemm>>>(k, Wk, nullptr, Kp, MROWS, EMB, EMB);
    sgemm_nt_kernel<<<gGemm, bGemm>>>(v, Wv, nullptr, Vp, MROWS, EMB, EMB);

    dim3 gAttn(S_LEN / BR, BATCH * NHEAD); // (16, 64)
    attn_kernel<<<gAttn, 128, smem_attn>>>(Qp, Kp, Vp, mask, Ctx);

    sgemm_nt_kernel<<<gGemm, bGemm>>>(Ctx, Wo, bo, out, MROWS, EMB, EMB);
}

// round 3
// speedup vs baseline: 1.4452x; 1.4452x over previous
#include <cuda_runtime.h>
#include <cuda_bf16.h>
#include <cstdint>

typedef unsigned long long ull;

// ===========================================================================
// Packed fp32x2 helpers (attention kernel)
// ===========================================================================
__device__ __forceinline__ void fma2(ull& d, ull a, ull b) {
    asm("fma.rn.f32x2 %0, %1, %2, %0;" : "+l"(d) : "l"(a), "l"(b));
}
__device__ __forceinline__ void mul2(ull& d, ull a) {
    asm("mul.rn.f32x2 %0, %0, %1;" : "+l"(d) : "l"(a));
}
__device__ __forceinline__ ull dup2(float x) {
    ull r; asm("mov.b64 %0, {%1, %1};" : "=l"(r) : "f"(x)); return r;
}
__device__ __forceinline__ void unpack2(ull v, float& lo, float& hi) {
    asm("mov.b64 {%0, %1}, %2;" : "=f"(lo), "=f"(hi) : "l"(v));
}

// ===========================================================================
// mma.sync / ldmatrix / cp.async helpers (base sm_103 target — no tcgen05)
// ===========================================================================
__device__ __forceinline__ uint32_t smem_u32_of(const void* p) {
    uint32_t a;
    asm("{ .reg .u64 t; cvta.to.shared.u64 t, %1; cvt.u32.u64 %0, t; }"
        : "=r"(a) : "l"(p));
    return a;
}
__device__ __forceinline__ void ldsm4(uint32_t r[4], uint32_t addr) {
    asm volatile("ldmatrix.sync.aligned.m8n8.x4.shared.b16 {%0,%1,%2,%3}, [%4];"
        : "=r"(r[0]), "=r"(r[1]), "=r"(r[2]), "=r"(r[3]) : "r"(addr));
}
__device__ __forceinline__ void mma16816(float c[4], const uint32_t a[4],
                                         const uint32_t b[2]) {
    asm volatile(
        "mma.sync.aligned.m16n8k16.row.col.f32.bf16.bf16.f32 "
        "{%0,%1,%2,%3}, {%4,%5,%6,%7}, {%8,%9}, {%0,%1,%2,%3};"
        : "+f"(c[0]), "+f"(c[1]), "+f"(c[2]), "+f"(c[3])
        : "r"(a[0]), "r"(a[1]), "r"(a[2]), "r"(a[3]), "r"(b[0]), "r"(b[1]));
}
__device__ __forceinline__ void cp16(uint32_t dst, const void* src) {
    asm volatile("cp.async.cg.shared.global [%0], [%1], 16;" :: "r"(dst), "l"(src));
}
#define CP_COMMIT() asm volatile("cp.async.commit_group;" ::: "memory")
template <int N>
__device__ __forceinline__ void cp_wait() {
    asm volatile("cp.async.wait_group %0;" :: "n"(N) : "memory");
}

// ===========================================================================
// Problem constants
// ===========================================================================
#define BATCH   4
#define S_LEN   2048
#define EMB     1024
#define NHEAD   16
#define DHEAD   64
#define MROWS   (BATCH * S_LEN)   // 8192

// Scratch (device globals — allocations forbidden)
__device__ float g_Qp[MROWS * EMB];
__device__ float g_Kp[MROWS * EMB];
__device__ float g_Vp[MROWS * EMB];
__device__ float g_Ctx[MROWS * EMB];
__device__ __nv_bfloat16 g_Ahi[MROWS * EMB];
__device__ __nv_bfloat16 g_Alo[MROWS * EMB];
__device__ __nv_bfloat16 g_Bhi[EMB * EMB];
__device__ __nv_bfloat16 g_Blo[EMB * EMB];

// ===========================================================================
// fp32 -> (bf16 hi, bf16 lo) split conversion
// ===========================================================================
__global__ __launch_bounds__(256) void cvt_split_kernel(
    const float* __restrict__ x, __nv_bfloat16* __restrict__ hi,
    __nv_bfloat16* __restrict__ lo, int n4)
{
    int i = blockIdx.x * blockDim.x + threadIdx.x;
    if (i >= n4) return;
    float4 v = ((const float4*)x)[i];
    __nv_bfloat16 h0 = __float2bfloat16(v.x);
    __nv_bfloat16 h1 = __float2bfloat16(v.y);
    __nv_bfloat16 h2 = __float2bfloat16(v.z);
    __nv_bfloat16 h3 = __float2bfloat16(v.w);
    __nv_bfloat16 l0 = __float2bfloat16(v.x - __bfloat162float(h0));
    __nv_bfloat16 l1 = __float2bfloat16(v.y - __bfloat162float(h1));
    __nv_bfloat16 l2 = __float2bfloat16(v.z - __bfloat162float(h2));
    __nv_bfloat16 l3 = __float2bfloat16(v.w - __bfloat162float(h3));
    __nv_bfloat162 hp0 = __nv_bfloat162(h0, h1), hp1 = __nv_bfloat162(h2, h3);
    __nv_bfloat162 lp0 = __nv_bfloat162(l0, l1), lp1 = __nv_bfloat162(l2, l3);
    ((uint2*)hi)[i] = make_uint2(*(uint32_t*)&hp0, *(uint32_t*)&hp1);
    ((uint2*)lo)[i] = make_uint2(*(uint32_t*)&lp0, *(uint32_t*)&lp1);
}

// ===========================================================================
// Split-bf16 3-term GEMM via mma.sync:
//   C[8192,1024] = A*B^T (+bias) = Ahi*Bhi^T + Alo*Bhi^T + Ahi*Blo^T
// CTA 128x128, BK=64, 8 warps (2x4), warp tile 64x32, 3-stage cp.async.
// SW128 swizzle shared layout; frags reused across the 3 terms.
// ===========================================================================
#define CHUNKS 16
#define STG_BYTES 65536            // Ahi|Alo|Bhi|Blo each 16KB
#define NSTAGE 3
#define GSMEM (NSTAGE * STG_BYTES) // 196608

__global__ __launch_bounds__(256, 1) void gemm3_kernel(
    const __nv_bfloat16* __restrict__ Ahi, const __nv_bfloat16* __restrict__ Alo,
    const __nv_bfloat16* __restrict__ Bhi, const __nv_bfloat16* __restrict__ Blo,
    const float* __restrict__ bias, float* __restrict__ C)
{
    extern __shared__ __align__(1024) char smem[];
    const uint32_t sb = smem_u32_of(smem);
    const int t = threadIdx.x;
    const int bm = blockIdx.y * 128;
    const int bn = blockIdx.x * 128;
    const int w = t >> 5, lane = t & 31;
    const int wm = (w >> 2) * 64;       // 0 or 64
    const int wn = (w & 3) * 32;        // 0,32,64,96

    // ---- loader mapping: 4 x 16B per thread per 16KB tile ----
    uint32_t lsw[4]; uint32_t lgo[4];
    #pragma unroll
    for (int i = 0; i < 4; i++) {
        int u = t + 256 * i;            // 0..1023
        int row = u >> 3, ku = u & 7;
        uint32_t off = row * 128 + ku * 16;
        lsw[i] = off ^ ((off >> 3) & 0x70);
        lgo[i] = (uint32_t)row * EMB + ku * 8;
    }
    const __nv_bfloat16* gAhi = Ahi + (size_t)bm * EMB;
    const __nv_bfloat16* gAlo = Alo + (size_t)bm * EMB;
    const __nv_bfloat16* gBhi = Bhi + (size_t)bn * EMB;
    const __nv_bfloat16* gBlo = Blo + (size_t)bn * EMB;

    // ---- ldmatrix per-thread base offsets (within a stage) ----
    const uint32_t xr  = (lane & 7) << 4;
    const uint32_t ak0 = (uint32_t)(lane & 16) ^ xr;
    const int      arow = lane & 15;
    const uint32_t bk0 = (uint32_t)((lane & 8) << 1) ^ xr;
    const int      brow = (lane & 7) | ((lane & 16) >> 1);
    uint32_t baA[4], baB[2];
    #pragma unroll
    for (int mi = 0; mi < 4; mi++)
        baA[mi] = (uint32_t)(wm + mi * 16 + arow) * 128 + ak0;
    #pragma unroll
    for (int nt = 0; nt < 2; nt++)
        baB[nt] = 32768u + (uint32_t)(wn + nt * 16 + brow) * 128 + bk0;

    float acc[4][4][4];
    #pragma unroll
    for (int mi = 0; mi < 4; mi++)
        #pragma unroll
        for (int ni = 0; ni < 4; ni++)
            #pragma unroll
            for (int r = 0; r < 4; r++) acc[mi][ni][r] = 0.0f;

    // ---- chunk loader ----
    auto load_chunk = [&](int c) {
        const uint32_t so = sb + (uint32_t)(c % NSTAGE) * STG_BYTES;
        const uint32_t ko = (uint32_t)c * 64;
        #pragma unroll
        for (int i = 0; i < 4; i++) {
            cp16(so +      0 + lsw[i], gAhi + lgo[i] + ko);
            cp16(so + 16384u + lsw[i], gAlo + lgo[i] + ko);
            cp16(so + 32768u + lsw[i], gBhi + lgo[i] + ko);
            cp16(so + 49152u + lsw[i], gBlo + lgo[i] + ko);
        }
        CP_COMMIT();
    };

    load_chunk(0);
    load_chunk(1);

    for (int c = 0; c < CHUNKS; c++) {
        if (c + 2 < CHUNKS) { load_chunk(c + 2); cp_wait<2>(); }
        else if (c + 1 < CHUNKS) { cp_wait<1>(); }
        else { cp_wait<0>(); }
        __syncthreads();

        const uint32_t so = sb + (uint32_t)(c % NSTAGE) * STG_BYTES;
        #pragma unroll
        for (int ks = 0; ks < 4; ks++) {
            const uint32_t kx = (uint32_t)ks << 5;
            uint32_t ahi[4][4], alo[4][4], bhi[2][4], blo[2][4];
            #pragma unroll
            for (int mi = 0; mi < 4; mi++) {
                ldsm4(ahi[mi], so + (baA[mi] ^ kx));
                ldsm4(alo[mi], so + 16384u + (baA[mi] ^ kx));
            }
            #pragma unroll
            for (int nt = 0; nt < 2; nt++) {
                ldsm4(bhi[nt], so + (baB[nt] ^ kx));
                ldsm4(blo[nt], so + 16384u + (baB[nt] ^ kx));
            }
            #pragma unroll
            for (int mi = 0; mi < 4; mi++)
                #pragma unroll
                for (int ni = 0; ni < 4; ni++) {
                    const uint32_t* bh = &bhi[ni >> 1][(ni & 1) * 2];
                    const uint32_t* bl = &blo[ni >> 1][(ni & 1) * 2];
                    mma16816(acc[mi][ni], ahi[mi], bh);
                    mma16816(acc[mi][ni], alo[mi], bh);
                    mma16816(acc[mi][ni], ahi[mi], bl);
                }
        }
        __syncthreads();
    }

    // ---- epilogue: frag regs -> gmem (float2), optional bias ----
    #pragma unroll
    for (int mi = 0; mi < 4; mi++) {
        #pragma unroll
        for (int ni = 0; ni < 4; ni++) {
            int row = bm + wm + mi * 16 + (lane >> 2);
            int col = bn + wn + ni * 8 + (lane & 3) * 2;
            float2 v0 = make_float2(acc[mi][ni][0], acc[mi][ni][1]);
            float2 v1 = make_float2(acc[mi][ni][2], acc[mi][ni][3]);
            if (bias) {
                float b0 = __ldg(bias + col), b1 = __ldg(bias + col + 1);
                v0.x += b0; v0.y += b1; v1.x += b0; v1.y += b1;
            }
            *(float2*)&C[(size_t)row * EMB + col] = v0;
            *(float2*)&C[(size_t)(row + 8) * EMB + col] = v1;
        }
    }
}

// ===========================================================================
// Flash attention, fp32, f32x2-packed (identical to round-1 passing version)
// ===========================================================================
#define BR 128
#define BC 64

__global__ __launch_bounds__(128) void attn_kernel(
    const float* __restrict__ Qp, const float* __restrict__ Kp,
    const float* __restrict__ Vp, const int* __restrict__ mask,
    float* __restrict__ Ctx)
{
    extern __shared__ float sm[];
    float* QsT = sm;                         // [64][128]
    float* KsT = sm + 64 * 128;              // [64][64]
    float* Vs  = KsT + 64 * 64;              // [64][64]
    int*   msk = (int*)(Vs + 64 * 64);       // [64]

    const int t  = threadIdx.x;
    const int qt = blockIdx.x;
    const int bh = blockIdx.y;
    const int b  = bh >> 4;
    const int h  = bh & 15;
    const int q0 = qt * BR;

    {
        const float* Qbase = Qp + ((size_t)(b * S_LEN + q0)) * EMB + h * DHEAD;
        #pragma unroll
        for (int i = 0; i < 16; i++) {
            int f  = t + 128 * i;
            int d4 = f >> 7;
            int q  = f & 127;
            float4 v = *(const float4*)(Qbase + (size_t)q * EMB + d4 * 4);
            QsT[(d4 * 4 + 0) * 128 + q] = v.x;
            QsT[(d4 * 4 + 1) * 128 + q] = v.y;
            QsT[(d4 * 4 + 2) * 128 + q] = v.z;
            QsT[(d4 * 4 + 3) * 128 + q] = v.w;
        }
    }

    ull o2[32];
    #pragma unroll
    for (int i = 0; i < 32; i++) o2[i] = 0ull;
    float m_run = -1e30f, l_run = 0.0f;

    for (int kt = 0; kt < S_LEN / BC; kt++) {
        const int k0 = kt * BC;
        __syncthreads();

        const float* Kbase = Kp + ((size_t)(b * S_LEN + k0)) * EMB + h * DHEAD;
        const float* Vbase = Vp + ((size_t)(b * S_LEN + k0)) * EMB + h * DHEAD;
        #pragma unroll
        for (int i = 0; i < 8; i++) {
            int f = t + 128 * i;
            int d4  = f >> 6;
            int key = f & 63;
            float4 kv = *(const float4*)(Kbase + (size_t)key * EMB + d4 * 4);
            KsT[(d4 * 4 + 0) * 64 + key] = kv.x;
            KsT[(d4 * 4 + 1) * 64 + key] = kv.y;
            KsT[(d4 * 4 + 2) * 64 + key] = kv.z;
            KsT[(d4 * 4 + 3) * 64 + key] = kv.w;
            int vk  = f >> 4;
            int vd4 = f & 15;
            float4 vv = *(const float4*)(Vbase + (size_t)vk * EMB + vd4 * 4);
            *(float4*)&Vs[vk * 64 + vd4 * 4] = vv;
        }
        if (t < 64) msk[t] = mask[b * S_LEN + k0 + t];
        __syncthreads();

        ull s2[32];
        #pragma unroll
        for (int j2 = 0; j2 < 32; j2++) s2[j2] = 0ull;
        #pragma unroll 8
        for (int d = 0; d < 64; d++) {
            ull qd = dup2(QsT[d * 128 + t]);
            const ulonglong2* kr = (const ulonglong2*)&KsT[d * 64];
            #pragma unroll
            for (int j4 = 0; j4 < 16; j4++) {
                ulonglong2 kk = kr[j4];
                fma2(s2[j4 * 2 + 0], qd, kk.x);
                fma2(s2[j4 * 2 + 1], qd, kk.y);
            }
        }

        float sc[64];
        #pragma unroll
        for (int j2 = 0; j2 < 32; j2++)
            unpack2(s2[j2], sc[2 * j2], sc[2 * j2 + 1]);

        float mx = m_run;
        #pragma unroll
        for (int j = 0; j < 64; j++) {
            sc[j] = msk[j] ? sc[j] * 0.125f : -1e10f;
            mx = fmaxf(mx, sc[j]);
        }
        float corr = __expf(m_run - mx);
        m_run = mx;
        float lsum = 0.0f;
        #pragma unroll
        for (int j = 0; j < 64; j++) {
            float p = __expf(sc[j] - mx);
            sc[j] = p;
            lsum += p;
        }
        l_run = l_run * corr + lsum;

        ull c2 = dup2(corr);
        #pragma unroll
        for (int d2 = 0; d2 < 32; d2++) mul2(o2[d2], c2);

        #pragma unroll 8
        for (int j = 0; j < 64; j++) {
            ull p2 = dup2(sc[j]);
            const ulonglong2* vr = (const ulonglong2*)&Vs[j * 64];
            #pragma unroll
            for (int d4 = 0; d4 < 16; d4++) {
                ulonglong2 vv = vr[d4];
                fma2(o2[d4 * 2 + 0], p2, vv.x);
                fma2(o2[d4 * 2 + 1], p2, vv.y);
            }
        }
    }

    float inv = 1.0f / l_run;
    ull iv = dup2(inv);
    float* Crow = Ctx + ((size_t)(b * S_LEN + q0 + t)) * EMB + h * DHEAD;
    #pragma unroll
    for (int d2 = 0; d2 < 32; d2++) {
        mul2(o2[d2], iv);
        *(ull*)&Crow[d2 * 2] = o2[d2];
    }
}

// ===========================================================================
// Launch
// ===========================================================================
extern "C" void kernel_launch(void* const* d_in, const int* in_sizes, int n_in,
                              void* d_out, int out_size)
{
    const float* q    = (const float*)d_in[0];
    const float* k    = (const float*)d_in[1];
    const float* v    = (const float*)d_in[2];
    const int*   mask = (const int*)  d_in[3];
    const float* Wq   = (const float*)d_in[4];
    const float* Wk   = (const float*)d_in[5];
    const float* Wv   = (const float*)d_in[6];
    const float* Wo   = (const float*)d_in[7];
    const float* bo   = (const float*)d_in[8];
    float* out = (float*)d_out;

    float *Qp, *Kp, *Vp, *Ctx;
    __nv_bfloat16 *Ahi, *Alo, *Bhi, *Blo;
    cudaGetSymbolAddress((void**)&Qp,  g_Qp);
    cudaGetSymbolAddress((void**)&Kp,  g_Kp);
    cudaGetSymbolAddress((void**)&Vp,  g_Vp);
    cudaGetSymbolAddress((void**)&Ctx, g_Ctx);
    cudaGetSymbolAddress((void**)&Ahi, g_Ahi);
    cudaGetSymbolAddress((void**)&Alo, g_Alo);
    cudaGetSymbolAddress((void**)&Bhi, g_Bhi);
    cudaGetSymbolAddress((void**)&Blo, g_Blo);

    cudaFuncSetAttribute(gemm3_kernel,
                         cudaFuncAttributeMaxDynamicSharedMemorySize, GSMEM);
    const int smem_attn = (64 * 128 + 64 * 64 + 64 * 64) * 4 + 64 * 4;
    cudaFuncSetAttribute(attn_kernel,
                         cudaFuncAttributeMaxDynamicSharedMemorySize, smem_attn);

    const int nA4 = MROWS * EMB / 4;
    const int nW4 = EMB * EMB / 4;
    dim3 gGemm(EMB / 128, MROWS / 128);  // (8, 64)

    // Q projection
    cvt_split_kernel<<<(nA4 + 255) / 256, 256>>>(q, Ahi, Alo, nA4);
    cvt_split_kernel<<<(nW4 + 255) / 256, 256>>>(Wq, Bhi, Blo, nW4);
    gemm3_kernel<<<gGemm, 256, GSMEM>>>(Ahi, Alo, Bhi, Blo, nullptr, Qp);
    // K projection
    cvt_split_kernel<<<(nA4 + 255) / 256, 256>>>(k, Ahi, Alo, nA4);
    cvt_split_kernel<<<(nW4 + 255) / 256, 256>>>(Wk, Bhi, Blo, nW4);
    gemm3_kernel<<<gGemm, 256, GSMEM>>>(Ahi, Alo, Bhi, Blo, nullptr, Kp);
    // V projection
    cvt_split_kernel<<<(nA4 + 255) / 256, 256>>>(v, Ahi, Alo, nA4);
    cvt_split_kernel<<<(nW4 + 255) / 256, 256>>>(Wv, Bhi, Blo, nW4);
    gemm3_kernel<<<gGemm, 256, GSMEM>>>(Ahi, Alo, Bhi, Blo, nullptr, Vp);

    // attention
    dim3 gAttn(S_LEN / BR, BATCH * NHEAD);
    attn_kernel<<<gAttn, 128, smem_attn>>>(Qp, Kp, Vp, mask, Ctx);

    // output projection (+bias)
    cvt_split_kernel<<<(nA4 + 255) / 256, 256>>>(Ctx, Ahi, Alo, nA4);
    cvt_split_kernel<<<(nW4 + 255) / 256, 256>>>(Wo, Bhi, Blo, nW4);
    gemm3_kernel<<<gGemm, 256, GSMEM>>>(Ahi, Alo, Bhi, Blo, bo, out);
}

// round 4
// speedup vs baseline: 3.5672x; 2.4684x over previous
#include <cuda_runtime.h>
#include <cuda_bf16.h>
#include <cstdint>

typedef unsigned long long ull;

// ===========================================================================
// mma.sync / ldmatrix / cp.async helpers (base sm_103 target — no tcgen05)
// ===========================================================================
__device__ __forceinline__ uint32_t smem_u32_of(const void* p) {
    uint32_t a;
    asm("{ .reg .u64 t; cvta.to.shared.u64 t, %1; cvt.u32.u64 %0, t; }"
        : "=r"(a) : "l"(p));
    return a;
}
__device__ __forceinline__ void ldsm4(uint32_t r[4], uint32_t addr) {
    asm volatile("ldmatrix.sync.aligned.m8n8.x4.shared.b16 {%0,%1,%2,%3}, [%4];"
        : "=r"(r[0]), "=r"(r[1]), "=r"(r[2]), "=r"(r[3]) : "r"(addr));
}
__device__ __forceinline__ void ldsm4t(uint32_t r[4], uint32_t addr) {
    asm volatile("ldmatrix.sync.aligned.m8n8.x4.trans.shared.b16 {%0,%1,%2,%3}, [%4];"
        : "=r"(r[0]), "=r"(r[1]), "=r"(r[2]), "=r"(r[3]) : "r"(addr));
}
__device__ __forceinline__ void mma16816(float c[4], const uint32_t a[4],
                                         const uint32_t b[2]) {
    asm volatile(
        "mma.sync.aligned.m16n8k16.row.col.f32.bf16.bf16.f32 "
        "{%0,%1,%2,%3}, {%4,%5,%6,%7}, {%8,%9}, {%0,%1,%2,%3};"
        : "+f"(c[0]), "+f"(c[1]), "+f"(c[2]), "+f"(c[3])
        : "r"(a[0]), "r"(a[1]), "r"(a[2]), "r"(a[3]), "r"(b[0]), "r"(b[1]));
}
__device__ __forceinline__ void cp16(uint32_t dst, const void* src) {
    asm volatile("cp.async.cg.shared.global [%0], [%1], 16;" :: "r"(dst), "l"(src));
}
#define CP_COMMIT() asm volatile("cp.async.commit_group;" ::: "memory")
template <int N>
__device__ __forceinline__ void cp_wait() {
    asm volatile("cp.async.wait_group %0;" :: "n"(N) : "memory");
}

// pack two floats into bf16x2 (lo = a, hi = b) + residual bf16x2
__device__ __forceinline__ void pack_split(float a, float b, uint32_t& hi, uint32_t& lo) {
    asm("cvt.rn.bf16x2.f32 %0, %1, %2;" : "=r"(hi) : "f"(b), "f"(a));
    float ha = __uint_as_float(hi << 16);
    float hb = __uint_as_float(hi & 0xffff0000u);
    float ra = a - ha, rb = b - hb;
    asm("cvt.rn.bf16x2.f32 %0, %1, %2;" : "=r"(lo) : "f"(rb), "f"(ra));
}

// ===========================================================================
// Problem constants
// ===========================================================================
#define BATCH   4
#define S_LEN   2048
#define EMB     1024
#define NHEAD   16
#define DHEAD   64
#define MROWS   (BATCH * S_LEN)   // 8192

// Scratch (device globals — allocations forbidden)
__device__ __nv_bfloat16 g_Ahi[MROWS * EMB];
__device__ __nv_bfloat16 g_Alo[MROWS * EMB];
__device__ __nv_bfloat16 g_Bhi[EMB * EMB];
__device__ __nv_bfloat16 g_Blo[EMB * EMB];
__device__ __nv_bfloat16 g_Qhi[MROWS * EMB];
__device__ __nv_bfloat16 g_Qlo[MROWS * EMB];
__device__ __nv_bfloat16 g_Khi[MROWS * EMB];
__device__ __nv_bfloat16 g_Klo[MROWS * EMB];
__device__ __nv_bfloat16 g_Vhi[MROWS * EMB];
__device__ __nv_bfloat16 g_Vlo[MROWS * EMB];
__device__ __nv_bfloat16 g_Chi[MROWS * EMB];
__device__ __nv_bfloat16 g_Clo[MROWS * EMB];

// ===========================================================================
// fp32 -> (bf16 hi, bf16 lo) split conversion
// ===========================================================================
__global__ __launch_bounds__(256) void cvt_split_kernel(
    const float* __restrict__ x, __nv_bfloat16* __restrict__ hi,
    __nv_bfloat16* __restrict__ lo, int n4)
{
    int i = blockIdx.x * blockDim.x + threadIdx.x;
    if (i >= n4) return;
    float4 v = ((const float4*)x)[i];
    uint32_t h0, l0, h1, l1;
    pack_split(v.x, v.y, h0, l0);
    pack_split(v.z, v.w, h1, l1);
    ((uint2*)hi)[i] = make_uint2(h0, h1);
    ((uint2*)lo)[i] = make_uint2(l0, l1);
}

// ===========================================================================
// Split-bf16 3-term GEMM via mma.sync:
//   C[8192,1024] = A*B^T = Ahi*Bhi^T + Alo*Bhi^T + Ahi*Blo^T
// Output either fp32 (+bias) or split bf16 hi/lo.
// CTA 128x128, BK=64, 8 warps (2x4), warp tile 64x32, 3-stage cp.async.
// ===========================================================================
#define CHUNKS 16
#define STG_BYTES 65536
#define NSTAGE 3
#define GSMEM (NSTAGE * STG_BYTES)

__global__ __launch_bounds__(256, 1) void gemm3_kernel(
    const __nv_bfloat16* __restrict__ Ahi, const __nv_bfloat16* __restrict__ Alo,
    const __nv_bfloat16* __restrict__ Bhi, const __nv_bfloat16* __restrict__ Blo,
    const float* __restrict__ bias, float* __restrict__ Cf,
    __nv_bfloat16* __restrict__ Chi, __nv_bfloat16* __restrict__ Clo)
{
    extern __shared__ __align__(1024) char smem[];
    const uint32_t sb = smem_u32_of(smem);
    const int t = threadIdx.x;
    const int bm = blockIdx.y * 128;
    const int bn = blockIdx.x * 128;
    const int w = t >> 5, lane = t & 31;
    const int wm = (w >> 2) * 64;
    const int wn = (w & 3) * 32;

    uint32_t lsw[4]; uint32_t lgo[4];
    #pragma unroll
    for (int i = 0; i < 4; i++) {
        int u = t + 256 * i;
        int row = u >> 3, ku = u & 7;
        uint32_t off = row * 128 + ku * 16;
        lsw[i] = off ^ ((off >> 3) & 0x70);
        lgo[i] = (uint32_t)row * EMB + ku * 8;
    }
    const __nv_bfloat16* gAhi = Ahi + (size_t)bm * EMB;
    const __nv_bfloat16* gAlo = Alo + (size_t)bm * EMB;
    const __nv_bfloat16* gBhi = Bhi + (size_t)bn * EMB;
    const __nv_bfloat16* gBlo = Blo + (size_t)bn * EMB;

    const uint32_t xr  = (lane & 7) << 4;
    const uint32_t ak0 = (uint32_t)(lane & 16) ^ xr;
    const int      arow = lane & 15;
    const uint32_t bk0 = (uint32_t)((lane & 8) << 1) ^ xr;
    const int      brow = (lane & 7) | ((lane & 16) >> 1);
    uint32_t baA[4], baB[2];
    #pragma unroll
    for (int mi = 0; mi < 4; mi++)
        baA[mi] = (uint32_t)(wm + mi * 16 + arow) * 128 + ak0;
    #pragma unroll
    for (int nt = 0; nt < 2; nt++)
        baB[nt] = 32768u + (uint32_t)(wn + nt * 16 + brow) * 128 + bk0;

    float acc[4][4][4];
    #pragma unroll
    for (int mi = 0; mi < 4; mi++)
        #pragma unroll
        for (int ni = 0; ni < 4; ni++)
            #pragma unroll
            for (int r = 0; r < 4; r++) acc[mi][ni][r] = 0.0f;

    auto load_chunk = [&](int c) {
        const uint32_t so = sb + (uint32_t)(c % NSTAGE) * STG_BYTES;
        const uint32_t ko = (uint32_t)c * 64;
        #pragma unroll
        for (int i = 0; i < 4; i++) {
            cp16(so +      0 + lsw[i], gAhi + lgo[i] + ko);
            cp16(so + 16384u + lsw[i], gAlo + lgo[i] + ko);
            cp16(so + 32768u + lsw[i], gBhi + lgo[i] + ko);
            cp16(so + 49152u + lsw[i], gBlo + lgo[i] + ko);
        }
        CP_COMMIT();
    };

    load_chunk(0);
    load_chunk(1);

    for (int c = 0; c < CHUNKS; c++) {
        if (c + 2 < CHUNKS) { load_chunk(c + 2); cp_wait<2>(); }
        else if (c + 1 < CHUNKS) { cp_wait<1>(); }
        else { cp_wait<0>(); }
        __syncthreads();

        const uint32_t so = sb + (uint32_t)(c % NSTAGE) * STG_BYTES;
        #pragma unroll
        for (int ks = 0; ks < 4; ks++) {
            const uint32_t kx = (uint32_t)ks << 5;
            uint32_t ahi[4][4], alo[4][4], bhi[2][4], blo[2][4];
            #pragma unroll
            for (int mi = 0; mi < 4; mi++) {
                ldsm4(ahi[mi], so + (baA[mi] ^ kx));
                ldsm4(alo[mi], so + 16384u + (baA[mi] ^ kx));
            }
            #pragma unroll
            for (int nt = 0; nt < 2; nt++) {
                ldsm4(bhi[nt], so + (baB[nt] ^ kx));
                ldsm4(blo[nt], so + 16384u + (baB[nt] ^ kx));
            }
            #pragma unroll
            for (int mi = 0; mi < 4; mi++)
                #pragma unroll
                for (int ni = 0; ni < 4; ni++) {
                    const uint32_t* bh = &bhi[ni >> 1][(ni & 1) * 2];
                    const uint32_t* bl = &blo[ni >> 1][(ni & 1) * 2];
                    mma16816(acc[mi][ni], ahi[mi], bh);
                    mma16816(acc[mi][ni], alo[mi], bh);
                    mma16816(acc[mi][ni], ahi[mi], bl);
                }
        }
        __syncthreads();
    }

    // ---- epilogue ----
    #pragma unroll
    for (int mi = 0; mi < 4; mi++) {
        #pragma unroll
        for (int ni = 0; ni < 4; ni++) {
            int row = bm + wm + mi * 16 + (lane >> 2);
            int col = bn + wn + ni * 8 + (lane & 3) * 2;
            if (Cf) {
                float2 v0 = make_float2(acc[mi][ni][0], acc[mi][ni][1]);
                float2 v1 = make_float2(acc[mi][ni][2], acc[mi][ni][3]);
                if (bias) {
                    float b0 = __ldg(bias + col), b1 = __ldg(bias + col + 1);
                    v0.x += b0; v0.y += b1; v1.x += b0; v1.y += b1;
                }
                *(float2*)&Cf[(size_t)row * EMB + col] = v0;
                *(float2*)&Cf[(size_t)(row + 8) * EMB + col] = v1;
            } else {
                uint32_t hi, lo;
                pack_split(acc[mi][ni][0], acc[mi][ni][1], hi, lo);
                *(uint32_t*)&Chi[(size_t)row * EMB + col] = hi;
                *(uint32_t*)&Clo[(size_t)row * EMB + col] = lo;
                pack_split(acc[mi][ni][2], acc[mi][ni][3], hi, lo);
                *(uint32_t*)&Chi[(size_t)(row + 8) * EMB + col] = hi;
                *(uint32_t*)&Clo[(size_t)(row + 8) * EMB + col] = lo;
            }
        }
    }
}

// ===========================================================================
// Tensor-core flash attention, split-bf16 3-term for QK^T and PV.
// Grid (16, 64) = (q-tiles, b*h). 256 threads = 8 warps, warp = m16 rows.
// Br=128 queries, Bc=64 keys/tile, 3-stage cp.async K/V pipeline.
// ===========================================================================
#define ASTG 32768                      // Khi|Klo|Vhi|Vlo, 8KB each
#define ANST 3
#define MASKOFF (ANST * ASTG)           // 98304
#define ASMEM (MASKOFF + ANST * 256)    // 99072

__global__ __launch_bounds__(256, 1) void attn_mma_kernel(
    const __nv_bfloat16* __restrict__ Qhi, const __nv_bfloat16* __restrict__ Qlo,
    const __nv_bfloat16* __restrict__ Khi, const __nv_bfloat16* __restrict__ Klo,
    const __nv_bfloat16* __restrict__ Vhi, const __nv_bfloat16* __restrict__ Vlo,
    const int* __restrict__ mask,
    __nv_bfloat16* __restrict__ Chi, __nv_bfloat16* __restrict__ Clo)
{
    extern __shared__ __align__(1024) char smem[];
    const uint32_t sb = smem_u32_of(smem);
    const int t = threadIdx.x, w = t >> 5, lane = t & 31;
    const int qt = blockIdx.x, bh = blockIdx.y;
    const int b = bh >> 4, h = bh & 15;
    const int q0 = qt * 128;
    const int hcol = h * 64;

    // ---- stage Q into [0,32KB), extract frags, then region is reused ----
    {
        const size_t qbase = ((size_t)(b * S_LEN + q0)) * EMB + hcol;
        #pragma unroll
        for (int i = 0; i < 8; i++) {
            int u = t + 256 * i;          // 0..2047
            int arr = u >> 10;            // 0 hi, 1 lo
            int r = (u >> 3) & 127;
            int du = u & 7;
            uint32_t off = r * 128 + du * 16;
            uint32_t sw = off ^ ((off >> 3) & 0x70);
            const __nv_bfloat16* src = (arr ? Qlo : Qhi) + qbase + (size_t)r * EMB + du * 8;
            cp16(sb + (uint32_t)arr * 16384u + sw, src);
        }
        CP_COMMIT();
    }
    cp_wait<0>();
    __syncthreads();

    uint32_t qh[4][4], ql[4][4];
    {
        uint32_t off = (uint32_t)(w * 16 + (lane & 15)) * 128 + ((lane >> 4) * 16);
        uint32_t baQ = off ^ ((off >> 3) & 0x70);
        #pragma unroll
        for (int k16 = 0; k16 < 4; k16++) {
            ldsm4(qh[k16], sb + (baQ ^ (uint32_t)(k16 * 32)));
            ldsm4(ql[k16], sb + 16384u + (baQ ^ (uint32_t)(k16 * 32)));
        }
    }
    __syncthreads();

    // frag base addresses for K (normal) and V (trans)
    uint32_t baK, baV;
    {
        uint32_t keyk = (uint32_t)((lane & 7) | ((lane & 16) >> 1));
        uint32_t offk = keyk * 128 + (uint32_t)((lane & 8) << 1);
        baK = offk ^ ((offk >> 3) & 0x70);
        uint32_t keyv = (uint32_t)(lane & 15);
        uint32_t offv = keyv * 128 + (uint32_t)((lane >> 4) * 16);
        baV = offv ^ ((offv >> 3) & 0x70);
    }

    auto load_tile = [&](int kt, int stg) {
        const size_t gk = ((size_t)(b * S_LEN + kt * 64)) * EMB + hcol;
        const uint32_t sdst = sb + (uint32_t)stg * ASTG;
        #pragma unroll
        for (int i = 0; i < 8; i++) {
            int u = t + 256 * i;          // 0..2047
            int arr = u >> 9;             // 0 Khi,1 Klo,2 Vhi,3 Vlo
            int r = (u >> 3) & 63;
            int du = u & 7;
            uint32_t off = r * 128 + du * 16;
            uint32_t sw = off ^ ((off >> 3) & 0x70);
            const __nv_bfloat16* p =
                (arr < 2) ? (arr ? Klo : Khi) : ((arr == 2) ? Vhi : Vlo);
            cp16(sdst + (uint32_t)arr * 8192u + sw, p + gk + (size_t)r * EMB + du * 8);
        }
        if (t < 16)
            cp16(sb + MASKOFF + (uint32_t)stg * 256u + (uint32_t)t * 16u,
                 mask + b * S_LEN + kt * 64 + t * 4);
        CP_COMMIT();
    };

    float O[8][4];
    #pragma unroll
    for (int j = 0; j < 8; j++)
        #pragma unroll
        for (int r = 0; r < 4; r++) O[j][r] = 0.0f;
    float m0 = -1e30f, m1 = -1e30f, l0 = 0.0f, l1 = 0.0f;

    load_tile(0, 0);
    load_tile(1, 1);

    for (int kt = 0; kt < S_LEN / 64; kt++) {
        if (kt + 2 < S_LEN / 64) { load_tile(kt + 2, (kt + 2) % ANST); cp_wait<2>(); }
        else if (kt + 1 < S_LEN / 64) { cp_wait<1>(); }
        else { cp_wait<0>(); }
        __syncthreads();

        const uint32_t so = sb + (uint32_t)(kt % ANST) * ASTG;
        const int* mp = (const int*)(smem + MASKOFF + (kt % ANST) * 256);

        // ---- scores = Q K^T (3-term) ----
        float sc[8][4];
        #pragma unroll
        for (int j = 0; j < 8; j++)
            #pragma unroll
            for (int r = 0; r < 4; r++) sc[j][r] = 0.0f;

        #pragma unroll
        for (int k16 = 0; k16 < 4; k16++) {
            const uint32_t kx = (uint32_t)(k16 * 32);
            #pragma unroll
            for (int np = 0; np < 4; np++) {
                uint32_t kh[4], kl[4];
                ldsm4(kh, so + ((baK + (uint32_t)np * 2048u) ^ kx));
                ldsm4(kl, so + 8192u + ((baK + (uint32_t)np * 2048u) ^ kx));
                mma16816(sc[2 * np],     qh[k16], &kh[0]);
                mma16816(sc[2 * np],     ql[k16], &kh[0]);
                mma16816(sc[2 * np],     qh[k16], &kl[0]);
                mma16816(sc[2 * np + 1], qh[k16], &kh[2]);
                mma16816(sc[2 * np + 1], ql[k16], &kh[2]);
                mma16816(sc[2 * np + 1], qh[k16], &kl[2]);
            }
        }

        // ---- scale + mask + online softmax (fp32) ----
        const int c0 = (lane & 3) * 2;
        float rm0 = m0, rm1 = m1;
        #pragma unroll
        for (int j = 0; j < 8; j++) {
            int kc = j * 8 + c0;
            int mk0 = mp[kc], mk1 = mp[kc + 1];
            sc[j][0] = mk0 ? sc[j][0] * 0.125f : -1e10f;
            sc[j][1] = mk1 ? sc[j][1] * 0.125f : -1e10f;
            sc[j][2] = mk0 ? sc[j][2] * 0.125f : -1e10f;
            sc[j][3] = mk1 ? sc[j][3] * 0.125f : -1e10f;
            rm0 = fmaxf(rm0, fmaxf(sc[j][0], sc[j][1]));
            rm1 = fmaxf(rm1, fmaxf(sc[j][2], sc[j][3]));
        }
        rm0 = fmaxf(rm0, __shfl_xor_sync(0xffffffffu, rm0, 1));
        rm0 = fmaxf(rm0, __shfl_xor_sync(0xffffffffu, rm0, 2));
        rm1 = fmaxf(rm1, __shfl_xor_sync(0xffffffffu, rm1, 1));
        rm1 = fmaxf(rm1, __shfl_xor_sync(0xffffffffu, rm1, 2));
        float corr0 = __expf(m0 - rm0);
        float corr1 = __expf(m1 - rm1);
        m0 = rm0; m1 = rm1;
        float ls0 = 0.0f, ls1 = 0.0f;
        #pragma unroll
        for (int j = 0; j < 8; j++) {
            sc[j][0] = __expf(sc[j][0] - m0);
            sc[j][1] = __expf(sc[j][1] - m0);
            sc[j][2] = __expf(sc[j][2] - m1);
            sc[j][3] = __expf(sc[j][3] - m1);
            ls0 += sc[j][0] + sc[j][1];
            ls1 += sc[j][2] + sc[j][3];
        }
        ls0 += __shfl_xor_sync(0xffffffffu, ls0, 1);
        ls0 += __shfl_xor_sync(0xffffffffu, ls0, 2);
        ls1 += __shfl_xor_sync(0xffffffffu, ls1, 1);
        ls1 += __shfl_xor_sync(0xffffffffu, ls1, 2);
        l0 = l0 * corr0 + ls0;
        l1 = l1 * corr1 + ls1;
        #pragma unroll
        for (int j = 0; j < 8; j++) {
            O[j][0] *= corr0; O[j][1] *= corr0;
            O[j][2] *= corr1; O[j][3] *= corr1;
        }

        // ---- pack P into split a-frags (QK c-frag == PV a-frag layout) ----
        uint32_t ph[4][4], pl[4][4];
        #pragma unroll
        for (int kb = 0; kb < 4; kb++) {
            pack_split(sc[2 * kb][0],     sc[2 * kb][1],     ph[kb][0], pl[kb][0]);
            pack_split(sc[2 * kb][2],     sc[2 * kb][3],     ph[kb][1], pl[kb][1]);
            pack_split(sc[2 * kb + 1][0], sc[2 * kb + 1][1], ph[kb][2], pl[kb][2]);
            pack_split(sc[2 * kb + 1][2], sc[2 * kb + 1][3], ph[kb][3], pl[kb][3]);
        }

        // ---- O += P V (3-term), V via ldmatrix.trans ----
        #pragma unroll
        for (int kb = 0; kb < 4; kb++) {
            const uint32_t kadd = (uint32_t)kb * 2048u;
            #pragma unroll
            for (int dp = 0; dp < 4; dp++) {
                uint32_t vh[4], vl[4];
                const uint32_t dx = (uint32_t)(dp * 32);
                ldsm4t(vh, so + 16384u + ((baV + kadd) ^ dx));
                ldsm4t(vl, so + 24576u + ((baV + kadd) ^ dx));
                mma16816(O[2 * dp],     ph[kb], &vh[0]);
                mma16816(O[2 * dp],     pl[kb], &vh[0]);
                mma16816(O[2 * dp],     ph[kb], &vl[0]);
                mma16816(O[2 * dp + 1], ph[kb], &vh[2]);
                mma16816(O[2 * dp + 1], pl[kb], &vh[2]);
                mma16816(O[2 * dp + 1], ph[kb], &vl[2]);
            }
        }
        __syncthreads();
    }

    // ---- epilogue: O/l -> split bf16 Ctx ----
    float inv0 = 1.0f / l0, inv1 = 1.0f / l1;
    size_t row0 = (size_t)(b * S_LEN + q0 + w * 16 + (lane >> 2));
    size_t row1 = row0 + 8;
    #pragma unroll
    for (int j = 0; j < 8; j++) {
        int col = hcol + j * 8 + (lane & 3) * 2;
        uint32_t hi, lo;
        pack_split(O[j][0] * inv0, O[j][1] * inv0, hi, lo);
        *(uint32_t*)&Chi[row0 * EMB + col] = hi;
        *(uint32_t*)&Clo[row0 * EMB + col] = lo;
        pack_split(O[j][2] * inv1, O[j][3] * inv1, hi, lo);
        *(uint32_t*)&Chi[row1 * EMB + col] = hi;
        *(uint32_t*)&Clo[row1 * EMB + col] = lo;
    }
}

// ===========================================================================
// Launch
// ===========================================================================
extern "C" void kernel_launch(void* const* d_in, const int* in_sizes, int n_in,
                              void* d_out, int out_size)
{
    const float* q    = (const float*)d_in[0];
    const float* k    = (const float*)d_in[1];
    const float* v    = (const float*)d_in[2];
    const int*   mask = (const int*)  d_in[3];
    const float* Wq   = (const float*)d_in[4];
    const float* Wk   = (const float*)d_in[5];
    const float* Wv   = (const float*)d_in[6];
    const float* Wo   = (const float*)d_in[7];
    const float* bo   = (const float*)d_in[8];
    float* out = (float*)d_out;

    __nv_bfloat16 *Ahi, *Alo, *Bhi, *Blo;
    __nv_bfloat16 *Qhi, *Qlo, *Khi, *Klo, *Vhi, *Vlo, *Chi, *Clo;
    cudaGetSymbolAddress((void**)&Ahi, g_Ahi);
    cudaGetSymbolAddress((void**)&Alo, g_Alo);
    cudaGetSymbolAddress((void**)&Bhi, g_Bhi);
    cudaGetSymbolAddress((void**)&Blo, g_Blo);
    cudaGetSymbolAddress((void**)&Qhi, g_Qhi);
    cudaGetSymbolAddress((void**)&Qlo, g_Qlo);
    cudaGetSymbolAddress((void**)&Khi, g_Khi);
    cudaGetSymbolAddress((void**)&Klo, g_Klo);
    cudaGetSymbolAddress((void**)&Vhi, g_Vhi);
    cudaGetSymbolAddress((void**)&Vlo, g_Vlo);
    cudaGetSymbolAddress((void**)&Chi, g_Chi);
    cudaGetSymbolAddress((void**)&Clo, g_Clo);

    cudaFuncSetAttribute(gemm3_kernel,
                         cudaFuncAttributeMaxDynamicSharedMemorySize, GSMEM);
    cudaFuncSetAttribute(attn_mma_kernel,
                         cudaFuncAttributeMaxDynamicSharedMemorySize, ASMEM);

    const int nA4 = MROWS * EMB / 4;
    const int nW4 = EMB * EMB / 4;
    dim3 gGemm(EMB / 128, MROWS / 128);  // (8, 64)

    // Q projection -> split bf16
    cvt_split_kernel<<<(nA4 + 255) / 256, 256>>>(q, Ahi, Alo, nA4);
    cvt_split_kernel<<<(nW4 + 255) / 256, 256>>>(Wq, Bhi, Blo, nW4);
    gemm3_kernel<<<gGemm, 256, GSMEM>>>(Ahi, Alo, Bhi, Blo, nullptr, nullptr, Qhi, Qlo);
    // K projection
    cvt_split_kernel<<<(nA4 + 255) / 256, 256>>>(k, Ahi, Alo, nA4);
    cvt_split_kernel<<<(nW4 + 255) / 256, 256>>>(Wk, Bhi, Blo, nW4);
    gemm3_kernel<<<gGemm, 256, GSMEM>>>(Ahi, Alo, Bhi, Blo, nullptr, nullptr, Khi, Klo);
    // V projection
    cvt_split_kernel<<<(nA4 + 255) / 256, 256>>>(v, Ahi, Alo, nA4);
    cvt_split_kernel<<<(nW4 + 255) / 256, 256>>>(Wv, Bhi, Blo, nW4);
    gemm3_kernel<<<gGemm, 256, GSMEM>>>(Ahi, Alo, Bhi, Blo, nullptr, nullptr, Vhi, Vlo);

    // attention (tensor cores) -> split bf16 Ctx
    dim3 gAttn(S_LEN / 128, BATCH * NHEAD);   // (16, 64)
    attn_mma_kernel<<<gAttn, 256, ASMEM>>>(Qhi, Qlo, Khi, Klo, Vhi, Vlo, mask, Chi, Clo);

    // output projection (+bias) -> fp32
    cvt_split_kernel<<<(nW4 + 255) / 256, 256>>>(Wo, Bhi, Blo, nW4);
    gemm3_kernel<<<gGemm, 256, GSMEM>>>(Chi, Clo, Bhi, Blo, bo, out, nullptr, nullptr);
}

// round 5
// speedup vs baseline: 5.3841x; 1.5093x over previous
#include <cuda_runtime.h>
#include <cuda_bf16.h>
#include <cstdint>

typedef unsigned long long ull;

// ===========================================================================
// mma.sync / ldmatrix / cp.async helpers (base sm_103 target — no tcgen05)
// ===========================================================================
__device__ __forceinline__ uint32_t smem_u32_of(const void* p) {
    uint32_t a;
    asm("{ .reg .u64 t; cvta.to.shared.u64 t, %1; cvt.u32.u64 %0, t; }"
        : "=r"(a) : "l"(p));
    return a;
}
__device__ __forceinline__ void ldsm4(uint32_t r[4], uint32_t addr) {
    asm volatile("ldmatrix.sync.aligned.m8n8.x4.shared.b16 {%0,%1,%2,%3}, [%4];"
        : "=r"(r[0]), "=r"(r[1]), "=r"(r[2]), "=r"(r[3]) : "r"(addr));
}
__device__ __forceinline__ void ldsm4t(uint32_t r[4], uint32_t addr) {
    asm volatile("ldmatrix.sync.aligned.m8n8.x4.trans.shared.b16 {%0,%1,%2,%3}, [%4];"
        : "=r"(r[0]), "=r"(r[1]), "=r"(r[2]), "=r"(r[3]) : "r"(addr));
}
__device__ __forceinline__ void mma16816(float c[4], const uint32_t a[4],
                                         const uint32_t b[2]) {
    asm volatile(
        "mma.sync.aligned.m16n8k16.row.col.f32.bf16.bf16.f32 "
        "{%0,%1,%2,%3}, {%4,%5,%6,%7}, {%8,%9}, {%0,%1,%2,%3};"
        : "+f"(c[0]), "+f"(c[1]), "+f"(c[2]), "+f"(c[3])
        : "r"(a[0]), "r"(a[1]), "r"(a[2]), "r"(a[3]), "r"(b[0]), "r"(b[1]));
}
__device__ __forceinline__ void cp16(uint32_t dst, const void* src) {
    asm volatile("cp.async.cg.shared.global [%0], [%1], 16;" :: "r"(dst), "l"(src));
}
#define CP_COMMIT() asm volatile("cp.async.commit_group;" ::: "memory")
template <int N>
__device__ __forceinline__ void cp_wait() {
    asm volatile("cp.async.wait_group %0;" :: "n"(N) : "memory");
}

// pack two floats into bf16x2 (lo = a, hi = b) + residual bf16x2
__device__ __forceinline__ void pack_split(float a, float b, uint32_t& hi, uint32_t& lo) {
    asm("cvt.rn.bf16x2.f32 %0, %1, %2;" : "=r"(hi) : "f"(b), "f"(a));
    float ha = __uint_as_float(hi << 16);
    float hb = __uint_as_float(hi & 0xffff0000u);
    float ra = a - ha, rb = b - hb;
    asm("cvt.rn.bf16x2.f32 %0, %1, %2;" : "=r"(lo) : "f"(rb), "f"(ra));
}

// ===========================================================================
// Problem constants
// ===========================================================================
#define BATCH   4
#define S_LEN   2048
#define EMB     1024
#define NHEAD   16
#define DHEAD   64
#define MROWS   (BATCH * S_LEN)   // 8192

// Scratch (device globals — allocations forbidden)
__device__ __nv_bfloat16 g_Ahi[MROWS * EMB];
__device__ __nv_bfloat16 g_Alo[MROWS * EMB];
__device__ __nv_bfloat16 g_Bhi[EMB * EMB];
__device__ __nv_bfloat16 g_Blo[EMB * EMB];
__device__ __nv_bfloat16 g_Qhi[MROWS * EMB];
__device__ __nv_bfloat16 g_Qlo[MROWS * EMB];
__device__ __nv_bfloat16 g_Khi[MROWS * EMB];
__device__ __nv_bfloat16 g_Klo[MROWS * EMB];
__device__ __nv_bfloat16 g_Vhi[MROWS * EMB];
__device__ __nv_bfloat16 g_Vlo[MROWS * EMB];
__device__ __nv_bfloat16 g_Chi[MROWS * EMB];
__device__ __nv_bfloat16 g_Clo[MROWS * EMB];
__device__ int g_idx[BATCH * S_LEN];
__device__ int g_cnt[BATCH];

// ===========================================================================
// Stable mask compaction: per batch, idx[] = positions with mask==1, cnt = count
// ===========================================================================
__global__ __launch_bounds__(1024) void mask_compact_kernel(
    const int* __restrict__ mask, int* __restrict__ idx, int* __restrict__ cnt)
{
    const int b = blockIdx.x, t = threadIdx.x;
    const int wid = t >> 5, lane = t & 31;
    __shared__ int wsum[32], woff[32], chunk_total;
    int base = 0;
    #pragma unroll
    for (int half = 0; half < 2; half++) {
        int e = half * 1024 + t;
        int m = mask[b * S_LEN + e];
        unsigned bal = __ballot_sync(0xffffffffu, m != 0);
        int wtot = __popc(bal);
        int pos  = __popc(bal & ((1u << lane) - 1u));
        if (lane == 0) wsum[wid] = wtot;
        __syncthreads();
        if (t < 32) {
            int v = wsum[t], s = v;
            #pragma unroll
            for (int o = 1; o < 32; o <<= 1) {
                int u = __shfl_up_sync(0xffffffffu, s, o);
                if (t >= o) s += u;
            }
            woff[t] = s - v;
            if (t == 31) chunk_total = s;
        }
        __syncthreads();
        if (m) idx[b * S_LEN + base + woff[wid] + pos] = e;
        base += chunk_total;
        __syncthreads();
    }
    if (t == 0) cnt[b] = base;
}

// ===========================================================================
// fp32 -> (bf16 hi, bf16 lo) split conversion (dense)
// ===========================================================================
__global__ __launch_bounds__(256) void cvt_split_kernel(
    const float* __restrict__ x, __nv_bfloat16* __restrict__ hi,
    __nv_bfloat16* __restrict__ lo, int n4)
{
    int i = blockIdx.x * blockDim.x + threadIdx.x;
    if (i >= n4) return;
    float4 v = ((const float4*)x)[i];
    uint32_t h0, l0, h1, l1;
    pack_split(v.x, v.y, h0, l0);
    pack_split(v.z, v.w, h1, l1);
    ((uint2*)hi)[i] = make_uint2(h0, h1);
    ((uint2*)lo)[i] = make_uint2(l0, l1);
}

// ===========================================================================
// Row-gather + split cvt for K/V inputs: dst row (b,r) = src row (b, idx[b][r])
// for r < cnt[b], else zeros. Grid covers B*S rows x 256 float4.
// ===========================================================================
__global__ __launch_bounds__(256) void cvt_gather_kernel(
    const float* __restrict__ src, const int* __restrict__ idx,
    const int* __restrict__ cnt,
    __nv_bfloat16* __restrict__ hi, __nv_bfloat16* __restrict__ lo)
{
    int i = blockIdx.x * blockDim.x + threadIdx.x;   // float4 id, 2M total
    int rowq = i >> 8;            // dst row: b*2048 + r
    int c4 = i & 255;
    int b = rowq >> 11, r = rowq & 2047;
    uint2 hh = make_uint2(0u, 0u), ll = make_uint2(0u, 0u);
    if (r < cnt[b]) {
        int s = idx[b * S_LEN + r];
        float4 v = ((const float4*)(src + ((size_t)(b * S_LEN + s)) * EMB))[c4];
        pack_split(v.x, v.y, hh.x, ll.x);
        pack_split(v.z, v.w, hh.y, ll.y);
    }
    ((uint2*)hi)[(size_t)rowq * 256 + c4] = hh;
    ((uint2*)lo)[(size_t)rowq * 256 + c4] = ll;
}

// ===========================================================================
// Split-bf16 3-term GEMM via mma.sync:
//   C[8192,1024] = A*B^T = Ahi*Bhi^T + Alo*Bhi^T + Ahi*Blo^T
// Output fp32 (+bias) or split bf16 hi/lo.
// Optional per-batch row count (counts): CTAs with all rows >= count exit.
// ===========================================================================
#define CHUNKS 16
#define STG_BYTES 65536
#define NSTAGE 3
#define GSMEM (NSTAGE * STG_BYTES)

__global__ __launch_bounds__(256, 1) void gemm3_kernel(
    const __nv_bfloat16* __restrict__ Ahi, const __nv_bfloat16* __restrict__ Alo,
    const __nv_bfloat16* __restrict__ Bhi, const __nv_bfloat16* __restrict__ Blo,
    const float* __restrict__ bias, float* __restrict__ Cf,
    __nv_bfloat16* __restrict__ Chi, __nv_bfloat16* __restrict__ Clo,
    const int* __restrict__ counts)
{
    extern __shared__ __align__(1024) char smem[];
    const uint32_t sb = smem_u32_of(smem);
    const int t = threadIdx.x;
    const int bm = blockIdx.y * 128;
    const int bn = blockIdx.x * 128;

    if (counts && (bm & 2047) >= counts[bm >> 11]) return;

    const int w = t >> 5, lane = t & 31;
    const int wm = (w >> 2) * 64;
    const int wn = (w & 3) * 32;

    uint32_t lsw[4]; uint32_t lgo[4];
    #pragma unroll
    for (int i = 0; i < 4; i++) {
        int u = t + 256 * i;
        int row = u >> 3, ku = u & 7;
        uint32_t off = row * 128 + ku * 16;
        lsw[i] = off ^ ((off >> 3) & 0x70);
        lgo[i] = (uint32_t)row * EMB + ku * 8;
    }
    const __nv_bfloat16* gAhi = Ahi + (size_t)bm * EMB;
    const __nv_bfloat16* gAlo = Alo + (size_t)bm * EMB;
    const __nv_bfloat16* gBhi = Bhi + (size_t)bn * EMB;
    const __nv_bfloat16* gBlo = Blo + (size_t)bn * EMB;

    const uint32_t xr  = (lane & 7) << 4;
    const uint32_t ak0 = (uint32_t)(lane & 16) ^ xr;
    const int      arow = lane & 15;
    const uint32_t bk0 = (uint32_t)((lane & 8) << 1) ^ xr;
    const int      brow = (lane & 7) | ((lane & 16) >> 1);
    uint32_t baA[4], baB[2];
    #pragma unroll
    for (int mi = 0; mi < 4; mi++)
        baA[mi] = (uint32_t)(wm + mi * 16 + arow) * 128 + ak0;
    #pragma unroll
    for (int nt = 0; nt < 2; nt++)
        baB[nt] = 32768u + (uint32_t)(wn + nt * 16 + brow) * 128 + bk0;

    float acc[4][4][4];
    #pragma unroll
    for (int mi = 0; mi < 4; mi++)
        #pragma unroll
        for (int ni = 0; ni < 4; ni++)
            #pragma unroll
            for (int r = 0; r < 4; r++) acc[mi][ni][r] = 0.0f;

    auto load_chunk = [&](int c) {
        const uint32_t so = sb + (uint32_t)(c % NSTAGE) * STG_BYTES;
        const uint32_t ko = (uint32_t)c * 64;
        #pragma unroll
        for (int i = 0; i < 4; i++) {
            cp16(so +      0 + lsw[i], gAhi + lgo[i] + ko);
            cp16(so + 16384u + lsw[i], gAlo + lgo[i] + ko);
            cp16(so + 32768u + lsw[i], gBhi + lgo[i] + ko);
            cp16(so + 49152u + lsw[i], gBlo + lgo[i] + ko);
        }
        CP_COMMIT();
    };

    load_chunk(0);
    load_chunk(1);

    for (int c = 0; c < CHUNKS; c++) {
        if (c + 2 < CHUNKS) { load_chunk(c + 2); cp_wait<2>(); }
        else if (c + 1 < CHUNKS) { cp_wait<1>(); }
        else { cp_wait<0>(); }
        __syncthreads();

        const uint32_t so = sb + (uint32_t)(c % NSTAGE) * STG_BYTES;
        #pragma unroll
        for (int ks = 0; ks < 4; ks++) {
            const uint32_t kx = (uint32_t)ks << 5;
            uint32_t ahi[4][4], alo[4][4], bhi[2][4], blo[2][4];
            #pragma unroll
            for (int mi = 0; mi < 4; mi++) {
                ldsm4(ahi[mi], so + (baA[mi] ^ kx));
                ldsm4(alo[mi], so + 16384u + (baA[mi] ^ kx));
            }
            #pragma unroll
            for (int nt = 0; nt < 2; nt++) {
                ldsm4(bhi[nt], so + (baB[nt] ^ kx));
                ldsm4(blo[nt], so + 16384u + (baB[nt] ^ kx));
            }
            #pragma unroll
            for (int mi = 0; mi < 4; mi++)
                #pragma unroll
                for (int ni = 0; ni < 4; ni++) {
                    const uint32_t* bh = &bhi[ni >> 1][(ni & 1) * 2];
                    const uint32_t* bl = &blo[ni >> 1][(ni & 1) * 2];
                    mma16816(acc[mi][ni], ahi[mi], bh);
                    mma16816(acc[mi][ni], alo[mi], bh);
                    mma16816(acc[mi][ni], ahi[mi], bl);
                }
        }
        __syncthreads();
    }

    // ---- epilogue ----
    #pragma unroll
    for (int mi = 0; mi < 4; mi++) {
        #pragma unroll
        for (int ni = 0; ni < 4; ni++) {
            int row = bm + wm + mi * 16 + (lane >> 2);
            int col = bn + wn + ni * 8 + (lane & 3) * 2;
            if (Cf) {
                float2 v0 = make_float2(acc[mi][ni][0], acc[mi][ni][1]);
                float2 v1 = make_float2(acc[mi][ni][2], acc[mi][ni][3]);
                if (bias) {
                    float b0 = __ldg(bias + col), b1 = __ldg(bias + col + 1);
                    v0.x += b0; v0.y += b1; v1.x += b0; v1.y += b1;
                }
                *(float2*)&Cf[(size_t)row * EMB + col] = v0;
                *(float2*)&Cf[(size_t)(row + 8) * EMB + col] = v1;
            } else {
                uint32_t hi, lo;
                pack_split(acc[mi][ni][0], acc[mi][ni][1], hi, lo);
                *(uint32_t*)&Chi[(size_t)row * EMB + col] = hi;
                *(uint32_t*)&Clo[(size_t)row * EMB + col] = lo;
                pack_split(acc[mi][ni][2], acc[mi][ni][3], hi, lo);
                *(uint32_t*)&Chi[(size_t)(row + 8) * EMB + col] = hi;
                *(uint32_t*)&Clo[(size_t)(row + 8) * EMB + col] = lo;
            }
        }
    }
}

// ===========================================================================
// Tensor-core flash attention over COMPACTED keys (no mask array needed).
// Grid (16, 64) = (q-tiles, b*h). 256 threads = 8 warps, warp = m16 rows.
// Loop runs ceil(n_b/64) key tiles; boundary tile masked by key-index compare.
// ===========================================================================
#define ASTG 32768                      // Khi|Klo|Vhi|Vlo, 8KB each
#define ANST 3
#define ASMEM (ANST * ASTG)             // 98304

__global__ __launch_bounds__(256, 1) void attn_mma_kernel(
    const __nv_bfloat16* __restrict__ Qhi, const __nv_bfloat16* __restrict__ Qlo,
    const __nv_bfloat16* __restrict__ Khi, const __nv_bfloat16* __restrict__ Klo,
    const __nv_bfloat16* __restrict__ Vhi, const __nv_bfloat16* __restrict__ Vlo,
    const int* __restrict__ cnt,
    __nv_bfloat16* __restrict__ Chi, __nv_bfloat16* __restrict__ Clo)
{
    extern __shared__ __align__(1024) char smem[];
    const uint32_t sb = smem_u32_of(smem);
    const int t = threadIdx.x, w = t >> 5, lane = t & 31;
    const int qt = blockIdx.x, bh = blockIdx.y;
    const int b = bh >> 4, h = bh & 15;
    const int q0 = qt * 128;
    const int hcol = h * 64;
    const int n = cnt[b];
    const int ntiles = (n + 63) >> 6;

    // ---- stage Q into [0,32KB), extract frags ----
    {
        const size_t qbase = ((size_t)(b * S_LEN + q0)) * EMB + hcol;
        #pragma unroll
        for (int i = 0; i < 8; i++) {
            int u = t + 256 * i;
            int arr = u >> 10;
            int r = (u >> 3) & 127;
            int du = u & 7;
            uint32_t off = r * 128 + du * 16;
            uint32_t sw = off ^ ((off >> 3) & 0x70);
            const __nv_bfloat16* src = (arr ? Qlo : Qhi) + qbase + (size_t)r * EMB + du * 8;
            cp16(sb + (uint32_t)arr * 16384u + sw, src);
        }
        CP_COMMIT();
    }
    cp_wait<0>();
    __syncthreads();

    uint32_t qh[4][4], ql[4][4];
    {
        uint32_t off = (uint32_t)(w * 16 + (lane & 15)) * 128 + ((lane >> 4) * 16);
        uint32_t baQ = off ^ ((off >> 3) & 0x70);
        #pragma unroll
        for (int k16 = 0; k16 < 4; k16++) {
            ldsm4(qh[k16], sb + (baQ ^ (uint32_t)(k16 * 32)));
            ldsm4(ql[k16], sb + 16384u + (baQ ^ (uint32_t)(k16 * 32)));
        }
    }
    __syncthreads();

    uint32_t baK, baV;
    {
        uint32_t keyk = (uint32_t)((lane & 7) | ((lane & 16) >> 1));
        uint32_t offk = keyk * 128 + (uint32_t)((lane & 8) << 1);
        baK = offk ^ ((offk >> 3) & 0x70);
        uint32_t keyv = (uint32_t)(lane & 15);
        uint32_t offv = keyv * 128 + (uint32_t)((lane >> 4) * 16);
        baV = offv ^ ((offv >> 3) & 0x70);
    }

    auto load_tile = [&](int kt, int stg) {
        const size_t gk = ((size_t)(b * S_LEN + kt * 64)) * EMB + hcol;
        const uint32_t sdst = sb + (uint32_t)stg * ASTG;
        #pragma unroll
        for (int i = 0; i < 8; i++) {
            int u = t + 256 * i;
            int arr = u >> 9;             // 0 Khi,1 Klo,2 Vhi,3 Vlo
            int r = (u >> 3) & 63;
            int du = u & 7;
            uint32_t off = r * 128 + du * 16;
            uint32_t sw = off ^ ((off >> 3) & 0x70);
            const __nv_bfloat16* p =
                (arr < 2) ? (arr ? Klo : Khi) : ((arr == 2) ? Vhi : Vlo);
            cp16(sdst + (uint32_t)arr * 8192u + sw, p + gk + (size_t)r * EMB + du * 8);
        }
        CP_COMMIT();
    };

    float O[8][4];
    #pragma unroll
    for (int j = 0; j < 8; j++)
        #pragma unroll
        for (int r = 0; r < 4; r++) O[j][r] = 0.0f;
    float m0 = -1e30f, m1 = -1e30f, l0 = 0.0f, l1 = 0.0f;

    if (ntiles == 0) {   // degenerate: no unmasked keys (p ~ 0) — emit zeros
        size_t row0 = (size_t)(b * S_LEN + q0 + w * 16 + (lane >> 2));
        #pragma unroll
        for (int j = 0; j < 8; j++) {
            int col = hcol + j * 8 + (lane & 3) * 2;
            *(uint32_t*)&Chi[row0 * EMB + col] = 0u;
            *(uint32_t*)&Clo[row0 * EMB + col] = 0u;
            *(uint32_t*)&Chi[(row0 + 8) * EMB + col] = 0u;
            *(uint32_t*)&Clo[(row0 + 8) * EMB + col] = 0u;
        }
        return;
    }

    load_tile(0, 0);
    if (ntiles > 1) load_tile(1, 1);

    for (int kt = 0; kt < ntiles; kt++) {
        if (kt + 2 < ntiles) { load_tile(kt + 2, (kt + 2) % ANST); cp_wait<2>(); }
        else if (kt + 1 < ntiles) { cp_wait<1>(); }
        else { cp_wait<0>(); }
        __syncthreads();

        const uint32_t so = sb + (uint32_t)(kt % ANST) * ASTG;

        // ---- scores = Q K^T (3-term) ----
        float sc[8][4];
        #pragma unroll
        for (int j = 0; j < 8; j++)
            #pragma unroll
            for (int r = 0; r < 4; r++) sc[j][r] = 0.0f;

        #pragma unroll
        for (int k16 = 0; k16 < 4; k16++) {
            const uint32_t kx = (uint32_t)(k16 * 32);
            #pragma unroll
            for (int np = 0; np < 4; np++) {
                uint32_t kh[4], kl[4];
                ldsm4(kh, so + ((baK + (uint32_t)np * 2048u) ^ kx));
                ldsm4(kl, so + 8192u + ((baK + (uint32_t)np * 2048u) ^ kx));
                mma16816(sc[2 * np],     qh[k16], &kh[0]);
                mma16816(sc[2 * np],     ql[k16], &kh[0]);
                mma16816(sc[2 * np],     qh[k16], &kl[0]);
                mma16816(sc[2 * np + 1], qh[k16], &kh[2]);
                mma16816(sc[2 * np + 1], ql[k16], &kh[2]);
                mma16816(sc[2 * np + 1], qh[k16], &kl[2]);
            }
        }

        // ---- scale + boundary mask + online softmax ----
        const int c0 = (lane & 3) * 2;
        const int limit = n - kt * 64;      // valid local keys in this tile
        float rm0 = m0, rm1 = m1;
        #pragma unroll
        for (int j = 0; j < 8; j++) {
            int kc = j * 8 + c0;
            bool v0 = kc < limit, v1 = kc + 1 < limit;
            sc[j][0] = v0 ? sc[j][0] * 0.125f : -1e10f;
            sc[j][1] = v1 ? sc[j][1] * 0.125f : -1e10f;
            sc[j][2] = v0 ? sc[j][2] * 0.125f : -1e10f;
            sc[j][3] = v1 ? sc[j][3] * 0.125f : -1e10f;
            rm0 = fmaxf(rm0, fmaxf(sc[j][0], sc[j][1]));
            rm1 = fmaxf(rm1, fmaxf(sc[j][2], sc[j][3]));
        }
        rm0 = fmaxf(rm0, __shfl_xor_sync(0xffffffffu, rm0, 1));
        rm0 = fmaxf(rm0, __shfl_xor_sync(0xffffffffu, rm0, 2));
        rm1 = fmaxf(rm1, __shfl_xor_sync(0xffffffffu, rm1, 1));
        rm1 = fmaxf(rm1, __shfl_xor_sync(0xffffffffu, rm1, 2));
        float corr0 = __expf(m0 - rm0);
        float corr1 = __expf(m1 - rm1);
        m0 = rm0; m1 = rm1;
        float ls0 = 0.0f, ls1 = 0.0f;
        #pragma unroll
        for (int j = 0; j < 8; j++) {
            sc[j][0] = __expf(sc[j][0] - m0);
            sc[j][1] = __expf(sc[j][1] - m0);
            sc[j][2] = __expf(sc[j][2] - m1);
            sc[j][3] = __expf(sc[j][3] - m1);
            ls0 += sc[j][0] + sc[j][1];
            ls1 += sc[j][2] + sc[j][3];
        }
        ls0 += __shfl_xor_sync(0xffffffffu, ls0, 1);
        ls0 += __shfl_xor_sync(0xffffffffu, ls0, 2);
        ls1 += __shfl_xor_sync(0xffffffffu, ls1, 1);
        ls1 += __shfl_xor_sync(0xffffffffu, ls1, 2);
        l0 = l0 * corr0 + ls0;
        l1 = l1 * corr1 + ls1;
        #pragma unroll
        for (int j = 0; j < 8; j++) {
            O[j][0] *= corr0; O[j][1] *= corr0;
            O[j][2] *= corr1; O[j][3] *= corr1;
        }

        // ---- pack P into split a-frags ----
        uint32_t ph[4][4], pl[4][4];
        #pragma unroll
        for (int kb = 0; kb < 4; kb++) {
            pack_split(sc[2 * kb][0],     sc[2 * kb][1],     ph[kb][0], pl[kb][0]);
            pack_split(sc[2 * kb][2],     sc[2 * kb][3],     ph[kb][1], pl[kb][1]);
            pack_split(sc[2 * kb + 1][0], sc[2 * kb + 1][1], ph[kb][2], pl[kb][2]);
            pack_split(sc[2 * kb + 1][2], sc[2 * kb + 1][3], ph[kb][3], pl[kb][3]);
        }

        // ---- O += P V (3-term), V via ldmatrix.trans ----
        #pragma unroll
        for (int kb = 0; kb < 4; kb++) {
            const uint32_t kadd = (uint32_t)kb * 2048u;
            #pragma unroll
            for (int dp = 0; dp < 4; dp++) {
                uint32_t vh[4], vl[4];
                const uint32_t dx = (uint32_t)(dp * 32);
                ldsm4t(vh, so + 16384u + ((baV + kadd) ^ dx));
                ldsm4t(vl, so + 24576u + ((baV + kadd) ^ dx));
                mma16816(O[2 * dp],     ph[kb], &vh[0]);
                mma16816(O[2 * dp],     pl[kb], &vh[0]);
                mma16816(O[2 * dp],     ph[kb], &vl[0]);
                mma16816(O[2 * dp + 1], ph[kb], &vh[2]);
                mma16816(O[2 * dp + 1], pl[kb], &vh[2]);
                mma16816(O[2 * dp + 1], ph[kb], &vl[2]);
            }
        }
        __syncthreads();
    }

    // ---- epilogue: O/l -> split bf16 Ctx ----
    float inv0 = 1.0f / l0, inv1 = 1.0f / l1;
    size_t row0 = (size_t)(b * S_LEN + q0 + w * 16 + (lane >> 2));
    size_t row1 = row0 + 8;
    #pragma unroll
    for (int j = 0; j < 8; j++) {
        int col = hcol + j * 8 + (lane & 3) * 2;
        uint32_t hi, lo;
        pack_split(O[j][0] * inv0, O[j][1] * inv0, hi, lo);
        *(uint32_t*)&Chi[row0 * EMB + col] = hi;
        *(uint32_t*)&Clo[row0 * EMB + col] = lo;
        pack_split(O[j][2] * inv1, O[j][3] * inv1, hi, lo);
        *(uint32_t*)&Chi[row1 * EMB + col] = hi;
        *(uint32_t*)&Clo[row1 * EMB + col] = lo;
    }
}

// ===========================================================================
// Launch
// ===========================================================================
extern "C" void kernel_launch(void* const* d_in, const int* in_sizes, int n_in,
                              void* d_out, int out_size)
{
    const float* q    = (const float*)d_in[0];
    const float* k    = (const float*)d_in[1];
    const float* v    = (const float*)d_in[2];
    const int*   mask = (const int*)  d_in[3];
    const float* Wq   = (const float*)d_in[4];
    const float* Wk   = (const float*)d_in[5];
    const float* Wv   = (const float*)d_in[6];
    const float* Wo   = (const float*)d_in[7];
    const float* bo   = (const float*)d_in[8];
    float* out = (float*)d_out;

    __nv_bfloat16 *Ahi, *Alo, *Bhi, *Blo;
    __nv_bfloat16 *Qhi, *Qlo, *Khi, *Klo, *Vhi, *Vlo, *Chi, *Clo;
    int *idx, *cnt;
    cudaGetSymbolAddress((void**)&Ahi, g_Ahi);
    cudaGetSymbolAddress((void**)&Alo, g_Alo);
    cudaGetSymbolAddress((void**)&Bhi, g_Bhi);
    cudaGetSymbolAddress((void**)&Blo, g_Blo);
    cudaGetSymbolAddress((void**)&Qhi, g_Qhi);
    cudaGetSymbolAddress((void**)&Qlo, g_Qlo);
    cudaGetSymbolAddress((void**)&Khi, g_Khi);
    cudaGetSymbolAddress((void**)&Klo, g_Klo);
    cudaGetSymbolAddress((void**)&Vhi, g_Vhi);
    cudaGetSymbolAddress((void**)&Vlo, g_Vlo);
    cudaGetSymbolAddress((void**)&Chi, g_Chi);
    cudaGetSymbolAddress((void**)&Clo, g_Clo);
    cudaGetSymbolAddress((void**)&idx, g_idx);
    cudaGetSymbolAddress((void**)&cnt, g_cnt);

    cudaFuncSetAttribute(gemm3_kernel,
                         cudaFuncAttributeMaxDynamicSharedMemorySize, GSMEM);
    cudaFuncSetAttribute(attn_mma_kernel,
                         cudaFuncAttributeMaxDynamicSharedMemorySize, ASMEM);

    const int nA4 = MROWS * EMB / 4;
    const int nW4 = EMB * EMB / 4;
    dim3 gGemm(EMB / 128, MROWS / 128);  // (8, 64)

    // mask compaction (per batch)
    mask_compact_kernel<<<BATCH, 1024>>>(mask, idx, cnt);

    // Q projection (all rows) -> split bf16
    cvt_split_kernel<<<(nA4 + 255) / 256, 256>>>(q, Ahi, Alo, nA4);
    cvt_split_kernel<<<(nW4 + 255) / 256, 256>>>(Wq, Bhi, Blo, nW4);
    gemm3_kernel<<<gGemm, 256, GSMEM>>>(Ahi, Alo, Bhi, Blo, nullptr, nullptr, Qhi, Qlo, nullptr);

    // K projection (compacted rows only)
    cvt_gather_kernel<<<(nA4 + 255) / 256, 256>>>(k, idx, cnt, Ahi, Alo);
    cvt_split_kernel<<<(nW4 + 255) / 256, 256>>>(Wk, Bhi, Blo, nW4);
    gemm3_kernel<<<gGemm, 256, GSMEM>>>(Ahi, Alo, Bhi, Blo, nullptr, nullptr, Khi, Klo, cnt);

    // V projection (compacted rows only)
    cvt_gather_kernel<<<(nA4 + 255) / 256, 256>>>(v, idx, cnt, Ahi, Alo);
    cvt_split_kernel<<<(nW4 + 255) / 256, 256>>>(Wv, Bhi, Blo, nW4);
    gemm3_kernel<<<gGemm, 256, GSMEM>>>(Ahi, Alo, Bhi, Blo, nullptr, nullptr, Vhi, Vlo, cnt);

    // attention over compacted keys -> split bf16 Ctx
    dim3 gAttn(S_LEN / 128, BATCH * NHEAD);   // (16, 64)
    attn_mma_kernel<<<gAttn, 256, ASMEM>>>(Qhi, Qlo, Khi, Klo, Vhi, Vlo, cnt, Chi, Clo);

    // output projection (+bias) -> fp32
    cvt_split_kernel<<<(nW4 + 255) / 256, 256>>>(Wo, Bhi, Blo, nW4);
    gemm3_kernel<<<gGemm, 256, GSMEM>>>(Chi, Clo, Bhi, Blo, bo, out, nullptr, nullptr, nullptr);
}